// round 1
// baseline (speedup 1.0000x reference)
#include <cuda_runtime.h>
#include <cuda_bf16.h>

// LightGCN: 3x SpMM (COO, segment-sum) + residual average.
// N = 150000 nodes, dim 64, NNZ = 4.8M edges.
//
// Strategy: edge-parallel SpMM with vector reduction atomics
// (red.global.add.v4.f32), node features live in L2 (38.4MB/buffer).

constexpr int NUSERS = 100000;
constexpr int NITEMS = 50000;
constexpr int NNODES = 150000;          // NUSERS + NITEMS
constexpr int NNZ_E  = 4800000;
constexpr int FEAT4  = NNODES * 16;     // float4 elements per buffer (dim 64 = 16 x float4)

// Scratch buffers (device globals — no allocation allowed in kernel_launch).
__device__ float4 g_b0[FEAT4];
__device__ float4 g_b1[FEAT4];
__device__ float4 g_b2[FEAT4];
__device__ float4 g_b3[FEAT4];

// buf0 = concat(user_emb, item_emb); buf1..3 = 0
__global__ void init_kernel(const float4* __restrict__ user,
                            const float4* __restrict__ item) {
    int i = blockIdx.x * blockDim.x + threadIdx.x;
    if (i >= FEAT4) return;
    float4 v = (i < NUSERS * 16) ? user[i] : item[i - NUSERS * 16];
    g_b0[i] = v;
    float4 z = make_float4(0.f, 0.f, 0.f, 0.f);
    g_b1[i] = z;
    g_b2[i] = z;
    g_b3[i] = z;
}

// out[src] += val * in[dst], edge-parallel, 16 threads per edge (one float4 each).
__global__ void spmm_kernel(const int*   __restrict__ src,
                            const int*   __restrict__ dst,
                            const float* __restrict__ val,
                            const float4* __restrict__ in,
                            float4*       __restrict__ out) {
    int t = blockIdx.x * blockDim.x + threadIdx.x;   // < NNZ_E*16 = 76.8M (fits int)
    if (t >= NNZ_E * 16) return;
    int e = t >> 4;
    int c = t & 15;

    float w = __ldg(&val[e]);
    int   d = __ldg(&dst[e]);
    int   s = __ldg(&src[e]);

    float4 x = in[d * 16 + c];
    float4 m = make_float4(w * x.x, w * x.y, w * x.z, w * x.w);

    float4* p = out + (s * 16 + c);
    asm volatile("red.global.add.v4.f32 [%0], {%1,%2,%3,%4};"
                 :: "l"(p), "f"(m.x), "f"(m.y), "f"(m.z), "f"(m.w)
                 : "memory");
}

// out = 0.25 * (b0 + b1 + b2 + b3)
__global__ void final_kernel(float4* __restrict__ out) {
    int i = blockIdx.x * blockDim.x + threadIdx.x;
    if (i >= FEAT4) return;
    float4 a = g_b0[i];
    float4 b = g_b1[i];
    float4 c = g_b2[i];
    float4 d = g_b3[i];
    float4 r;
    r.x = 0.25f * (a.x + b.x + c.x + d.x);
    r.y = 0.25f * (a.y + b.y + c.y + d.y);
    r.z = 0.25f * (a.z + b.z + c.z + d.z);
    r.w = 0.25f * (a.w + b.w + c.w + d.w);
    out[i] = r;
}

extern "C" void kernel_launch(void* const* d_in, const int* in_sizes, int n_in,
                              void* d_out, int out_size) {
    const float4* user = (const float4*)d_in[0];
    const float4* item = (const float4*)d_in[1];
    const int*    esrc = (const int*)d_in[2];
    const int*    edst = (const int*)d_in[3];
    const float*  eval = (const float*)d_in[4];
    float4* out = (float4*)d_out;

    // Resolve scratch symbol addresses (host-side queries; capture-safe).
    float4 *b0, *b1, *b2, *b3;
    cudaGetSymbolAddress((void**)&b0, g_b0);
    cudaGetSymbolAddress((void**)&b1, g_b1);
    cudaGetSymbolAddress((void**)&b2, g_b2);
    cudaGetSymbolAddress((void**)&b3, g_b3);

    const int TB = 256;
    int init_blocks = (FEAT4 + TB - 1) / TB;
    int spmm_blocks = (NNZ_E * 16 + TB - 1) / TB;   // 300000

    init_kernel<<<init_blocks, TB>>>(user, item);

    spmm_kernel<<<spmm_blocks, TB>>>(esrc, edst, eval, b0, b1);
    spmm_kernel<<<spmm_blocks, TB>>>(esrc, edst, eval, b1, b2);
    spmm_kernel<<<spmm_blocks, TB>>>(esrc, edst, eval, b2, b3);

    final_kernel<<<init_blocks, TB>>>(out);
}

// round 3
// speedup vs baseline: 2.4223x; 2.4223x over previous
#include <cuda_runtime.h>
#include <cuda_bf16.h>

// LightGCN: CSR-based SpMM x3 + fused residual average.
// Counting-sort edges by src into CSR once per launch, then row-parallel
// SpMM (half-warp per row, float4 per lane, register acc, no feature
// atomics). Layer 3 fuses the (b0+b1+b2+b3)/4 epilogue. 4x edge unroll
// for memory-level parallelism against L2 hit latency.

constexpr int NUSERS = 100000;
constexpr int NITEMS = 50000;
constexpr int NNODES = 150000;
constexpr int NNZ_E  = 4800000;
constexpr int FEAT4  = NNODES * 16;   // 64 floats = 16 float4 per node

constexpr int SCAN_B    = 256;
constexpr int SCAN_NBLK = (NNODES + SCAN_B - 1) / SCAN_B;  // 586

// ---- scratch (device globals; no allocation allowed) ----
__device__ float4 g_b0[FEAT4];
__device__ float4 g_b1[FEAT4];
__device__ float4 g_b2[FEAT4];
__device__ int    g_cnt[NNODES];
__device__ int    g_rowptr[NNODES + 1];
__device__ int    g_rowcur[NNODES];
__device__ int    g_bsum[SCAN_NBLK];
__device__ int2   g_meta[NNZ_E];      // {dst, val bits} sorted by src

// ---------------- CSR build ----------------

__global__ void zero_counts() {
    int i = blockIdx.x * blockDim.x + threadIdx.x;
    if (i < NNODES) g_cnt[i] = 0;
}

__global__ void hist_kernel(const int* __restrict__ src) {
    int e = blockIdx.x * blockDim.x + threadIdx.x;
    if (e < NNZ_E) atomicAdd(&g_cnt[src[e]], 1);
}

__global__ void scan_local() {
    __shared__ int s[SCAN_B];
    int i = blockIdx.x * SCAN_B + threadIdx.x;
    int v = (i < NNODES) ? g_cnt[i] : 0;
    s[threadIdx.x] = v;
    __syncthreads();
    #pragma unroll
    for (int off = 1; off < SCAN_B; off <<= 1) {
        int x = (threadIdx.x >= off) ? s[threadIdx.x - off] : 0;
        __syncthreads();
        s[threadIdx.x] += x;
        __syncthreads();
    }
    int incl = s[threadIdx.x];
    if (i < NNODES) g_rowptr[i] = incl - v;          // local exclusive
    if (threadIdx.x == SCAN_B - 1) g_bsum[blockIdx.x] = incl;
}

__global__ void scan_sums() {
    __shared__ int s[1024];
    int t = threadIdx.x;
    int v = (t < SCAN_NBLK) ? g_bsum[t] : 0;
    s[t] = v;
    __syncthreads();
    #pragma unroll
    for (int off = 1; off < 1024; off <<= 1) {
        int x = (t >= off) ? s[t - off] : 0;
        __syncthreads();
        s[t] += x;
        __syncthreads();
    }
    if (t < SCAN_NBLK) g_bsum[t] = s[t] - v;         // exclusive
}

__global__ void scan_add() {
    int i = blockIdx.x * SCAN_B + threadIdx.x;
    if (i < NNODES) {
        int p = g_rowptr[i] + g_bsum[blockIdx.x];
        g_rowptr[i] = p;
        g_rowcur[i] = p;
    }
    if (i == 0) g_rowptr[NNODES] = NNZ_E;
}

__global__ void scatter_kernel(const int*   __restrict__ src,
                               const int*   __restrict__ dst,
                               const float* __restrict__ val) {
    int e = blockIdx.x * blockDim.x + threadIdx.x;
    if (e >= NNZ_E) return;
    int s = src[e];
    int pos = atomicAdd(&g_rowcur[s], 1);
    g_meta[pos] = make_int2(dst[e], __float_as_int(val[e]));
}

// ---------------- init: b0 = concat(user, item) ----------------

__global__ void init_kernel(const float4* __restrict__ user,
                            const float4* __restrict__ item) {
    int i = blockIdx.x * blockDim.x + threadIdx.x;
    if (i >= FEAT4) return;
    g_b0[i] = (i < NUSERS * 16) ? user[i] : item[i - NUSERS * 16];
}

// ---------------- row-parallel SpMM ----------------
// Half-warp per row: 16 lanes, each owns one float4 of the 64-dim feature.
// Edges walked sequentially with 4x unroll for memory-level parallelism.

__device__ __forceinline__ float4 spmm_row(const float4* __restrict__ in,
                                           int row, int lane) {
    int beg = g_rowptr[row];
    int end = g_rowptr[row + 1];
    float4 acc = make_float4(0.f, 0.f, 0.f, 0.f);
    int i = beg;
    for (; i + 4 <= end; i += 4) {
        int2 m0 = __ldg(&g_meta[i]);
        int2 m1 = __ldg(&g_meta[i + 1]);
        int2 m2 = __ldg(&g_meta[i + 2]);
        int2 m3 = __ldg(&g_meta[i + 3]);
        float4 x0 = __ldg(&in[m0.x * 16 + lane]);
        float4 x1 = __ldg(&in[m1.x * 16 + lane]);
        float4 x2 = __ldg(&in[m2.x * 16 + lane]);
        float4 x3 = __ldg(&in[m3.x * 16 + lane]);
        float w0 = __int_as_float(m0.y);
        float w1 = __int_as_float(m1.y);
        float w2 = __int_as_float(m2.y);
        float w3 = __int_as_float(m3.y);
        acc.x += w0 * x0.x; acc.y += w0 * x0.y;
        acc.z += w0 * x0.z; acc.w += w0 * x0.w;
        acc.x += w1 * x1.x; acc.y += w1 * x1.y;
        acc.z += w1 * x1.z; acc.w += w1 * x1.w;
        acc.x += w2 * x2.x; acc.y += w2 * x2.y;
        acc.z += w2 * x2.z; acc.w += w2 * x2.w;
        acc.x += w3 * x3.x; acc.y += w3 * x3.y;
        acc.z += w3 * x3.z; acc.w += w3 * x3.w;
    }
    for (; i < end; i++) {
        int2 m0 = __ldg(&g_meta[i]);
        float4 x0 = __ldg(&in[m0.x * 16 + lane]);
        float w0 = __int_as_float(m0.y);
        acc.x += w0 * x0.x; acc.y += w0 * x0.y;
        acc.z += w0 * x0.z; acc.w += w0 * x0.w;
    }
    return acc;
}

__global__ void spmm_kernel(const float4* __restrict__ in,
                            float4*       __restrict__ out) {
    int gtid = blockIdx.x * blockDim.x + threadIdx.x;
    int warp = gtid >> 5;
    int half = (threadIdx.x >> 4) & 1;
    int lane = threadIdx.x & 15;
    int row  = warp * 2 + half;
    if (row >= NNODES) return;
    out[row * 16 + lane] = spmm_row(in, row, lane);
}

// Layer 3 fused with epilogue: out = 0.25 * (b0 + b1 + b2 + spmm(b2))
__global__ void spmm_final_kernel(float4* __restrict__ out) {
    int gtid = blockIdx.x * blockDim.x + threadIdx.x;
    int warp = gtid >> 5;
    int half = (threadIdx.x >> 4) & 1;
    int lane = threadIdx.x & 15;
    int row  = warp * 2 + half;
    if (row >= NNODES) return;

    float4 acc = spmm_row(g_b2, row, lane);
    int idx = row * 16 + lane;
    float4 a = g_b0[idx];
    float4 b = g_b1[idx];
    float4 c = g_b2[idx];
    float4 r;
    r.x = 0.25f * (a.x + b.x + c.x + acc.x);
    r.y = 0.25f * (a.y + b.y + c.y + acc.y);
    r.z = 0.25f * (a.z + b.z + c.z + acc.z);
    r.w = 0.25f * (a.w + b.w + c.w + acc.w);
    out[idx] = r;
}

// ---------------- launch ----------------

extern "C" void kernel_launch(void* const* d_in, const int* in_sizes, int n_in,
                              void* d_out, int out_size) {
    const float4* user = (const float4*)d_in[0];
    const float4* item = (const float4*)d_in[1];
    const int*    esrc = (const int*)d_in[2];
    const int*    edst = (const int*)d_in[3];
    const float*  eval = (const float*)d_in[4];
    float4* out = (float4*)d_out;

    float4 *b0, *b1, *b2;
    cudaGetSymbolAddress((void**)&b0, g_b0);
    cudaGetSymbolAddress((void**)&b1, g_b1);
    cudaGetSymbolAddress((void**)&b2, g_b2);

    const int TB = 256;
    int node_blocks = (NNODES + TB - 1) / TB;            // 586
    int feat_blocks = (FEAT4 + TB - 1) / TB;             // 9375
    int edge_blocks = (NNZ_E + TB - 1) / TB;             // 18750
    int spmm_blocks = (NNODES / 2 * 32 + TB - 1) / TB;   // 9375 (half-warp per row)

    // CSR build
    zero_counts<<<node_blocks, TB>>>();
    hist_kernel<<<edge_blocks, TB>>>(esrc);
    scan_local<<<SCAN_NBLK, SCAN_B>>>();
    scan_sums<<<1, 1024>>>();
    scan_add<<<SCAN_NBLK, SCAN_B>>>();
    scatter_kernel<<<edge_blocks, TB>>>(esrc, edst, eval);

    // b0 = concat(user, item)
    init_kernel<<<feat_blocks, TB>>>(user, item);

    // 3 propagation layers; layer 3 fuses the residual average
    spmm_kernel<<<spmm_blocks, TB>>>(b0, b1);
    spmm_kernel<<<spmm_blocks, TB>>>(b1, b2);
    spmm_final_kernel<<<spmm_blocks, TB>>>(out);
}

// round 4
// speedup vs baseline: 2.6962x; 1.1131x over previous
#include <cuda_runtime.h>
#include <cuda_fp16.h>
#include <cuda_bf16.h>

// LightGCN: CSR SpMM x3 + fused residual average.
// Round 4: fp16 inter-layer gather buffers (halves L2 gather bytes — the
// measured binder at ~12.7TB/s LTS), fp32 running accumulator fed with
// pre-rounding sums so precision stays ~1e-4. 8 lanes/row, uint4 (8-half)
// loads, 4x edge unroll.

constexpr int NUSERS = 100000;
constexpr int NITEMS = 50000;
constexpr int NNODES = 150000;
constexpr int NNZ_E  = 4800000;
constexpr int FEAT4  = NNODES * 16;   // float4 per buffer
constexpr int HVEC   = NNODES * 8;    // uint4 (8 halves) per fp16 buffer

constexpr int SCAN_B    = 256;
constexpr int SCAN_NBLK = (NNODES + SCAN_B - 1) / SCAN_B;  // 586

// ---- scratch ----
__device__ uint4  g_h0[HVEC];         // fp16 features (ping)
__device__ uint4  g_h1[HVEC];         // fp16 features (pong)
__device__ float4 g_acc[FEAT4];       // fp32 running residual sum
__device__ int    g_cnt[NNODES];
__device__ int    g_rowptr[NNODES + 1];
__device__ int    g_rowcur[NNODES];
__device__ int    g_bsum[SCAN_NBLK];
__device__ int2   g_meta[NNZ_E];      // {dst, val bits} sorted by src

// ---------------- CSR build ----------------

__global__ void zero_counts() {
    int i = blockIdx.x * blockDim.x + threadIdx.x;
    if (i < NNODES) g_cnt[i] = 0;
}

__global__ void hist_kernel(const int* __restrict__ src) {
    int e = blockIdx.x * blockDim.x + threadIdx.x;
    if (e < NNZ_E) atomicAdd(&g_cnt[src[e]], 1);
}

__global__ void scan_local() {
    __shared__ int s[SCAN_B];
    int i = blockIdx.x * SCAN_B + threadIdx.x;
    int v = (i < NNODES) ? g_cnt[i] : 0;
    s[threadIdx.x] = v;
    __syncthreads();
    #pragma unroll
    for (int off = 1; off < SCAN_B; off <<= 1) {
        int x = (threadIdx.x >= off) ? s[threadIdx.x - off] : 0;
        __syncthreads();
        s[threadIdx.x] += x;
        __syncthreads();
    }
    int incl = s[threadIdx.x];
    if (i < NNODES) g_rowptr[i] = incl - v;
    if (threadIdx.x == SCAN_B - 1) g_bsum[blockIdx.x] = incl;
}

__global__ void scan_sums() {
    __shared__ int s[1024];
    int t = threadIdx.x;
    int v = (t < SCAN_NBLK) ? g_bsum[t] : 0;
    s[t] = v;
    __syncthreads();
    #pragma unroll
    for (int off = 1; off < 1024; off <<= 1) {
        int x = (t >= off) ? s[t - off] : 0;
        __syncthreads();
        s[t] += x;
        __syncthreads();
    }
    if (t < SCAN_NBLK) g_bsum[t] = s[t] - v;
}

__global__ void scan_add() {
    int i = blockIdx.x * SCAN_B + threadIdx.x;
    if (i < NNODES) {
        int p = g_rowptr[i] + g_bsum[blockIdx.x];
        g_rowptr[i] = p;
        g_rowcur[i] = p;
    }
    if (i == 0) g_rowptr[NNODES] = NNZ_E;
}

__global__ void scatter_kernel(const int*   __restrict__ src,
                               const int*   __restrict__ dst,
                               const float* __restrict__ val) {
    int e = blockIdx.x * blockDim.x + threadIdx.x;
    if (e >= NNZ_E) return;
    int s = src[e];
    int pos = atomicAdd(&g_rowcur[s], 1);
    g_meta[pos] = make_int2(dst[e], __float_as_int(val[e]));
}

// ---------------- init: h0 = fp16(concat), acc = concat ----------------

__global__ void init_kernel(const float4* __restrict__ user,
                            const float4* __restrict__ item) {
    int i = blockIdx.x * blockDim.x + threadIdx.x;   // one uint4 (8 halves)
    if (i >= HVEC) return;
    int j = i * 2;                                   // float4 index (linear concat)
    float4 a = (j     < NUSERS * 16) ? user[j]     : item[j - NUSERS * 16];
    float4 b = (j + 1 < NUSERS * 16) ? user[j + 1] : item[j + 1 - NUSERS * 16];
    g_acc[j]     = a;
    g_acc[j + 1] = b;
    union { uint4 u; __half2 h[4]; } o;
    o.h[0] = __floats2half2_rn(a.x, a.y);
    o.h[1] = __floats2half2_rn(a.z, a.w);
    o.h[2] = __floats2half2_rn(b.x, b.y);
    o.h[3] = __floats2half2_rn(b.z, b.w);
    g_h0[i] = o.u;
}

// ---------------- SpMM core: 8 lanes/row, 8 floats/lane ----------------

struct Acc8 { float v[8]; };

__device__ __forceinline__ void fma8(Acc8& a, float w, uint4 u) {
    union { uint4 u; __half2 h[4]; } x;
    x.u = u;
    #pragma unroll
    for (int k = 0; k < 4; k++) {
        float2 f = __half22float2(x.h[k]);
        a.v[2*k]   += w * f.x;
        a.v[2*k+1] += w * f.y;
    }
}

__device__ __forceinline__ Acc8 spmm_row(const uint4* __restrict__ in,
                                         int row, int lane) {
    int beg = __ldg(&g_rowptr[row]);
    int end = __ldg(&g_rowptr[row + 1]);
    Acc8 acc;
    #pragma unroll
    for (int k = 0; k < 8; k++) acc.v[k] = 0.f;
    int i = beg;
    for (; i + 4 <= end; i += 4) {
        int2 m0 = __ldg(&g_meta[i]);
        int2 m1 = __ldg(&g_meta[i + 1]);
        int2 m2 = __ldg(&g_meta[i + 2]);
        int2 m3 = __ldg(&g_meta[i + 3]);
        uint4 x0 = __ldg(&in[m0.x * 8 + lane]);
        uint4 x1 = __ldg(&in[m1.x * 8 + lane]);
        uint4 x2 = __ldg(&in[m2.x * 8 + lane]);
        uint4 x3 = __ldg(&in[m3.x * 8 + lane]);
        fma8(acc, __int_as_float(m0.y), x0);
        fma8(acc, __int_as_float(m1.y), x1);
        fma8(acc, __int_as_float(m2.y), x2);
        fma8(acc, __int_as_float(m3.y), x3);
    }
    for (; i < end; i++) {
        int2 m = __ldg(&g_meta[i]);
        uint4 x = __ldg(&in[m.x * 8 + lane]);
        fma8(acc, __int_as_float(m.y), x);
    }
    return acc;
}

// Layers 1,2: s = A*in ; out_h = fp16(s) ; acc += s (pre-rounding fp32)
__global__ void spmm_kernel(const uint4* __restrict__ in,
                            uint4*       __restrict__ out_h) {
    int gtid = blockIdx.x * blockDim.x + threadIdx.x;
    int row  = gtid >> 3;
    int lane = gtid & 7;
    if (row >= NNODES) return;

    Acc8 s = spmm_row(in, row, lane);

    union { uint4 u; __half2 h[4]; } o;
    o.h[0] = __floats2half2_rn(s.v[0], s.v[1]);
    o.h[1] = __floats2half2_rn(s.v[2], s.v[3]);
    o.h[2] = __floats2half2_rn(s.v[4], s.v[5]);
    o.h[3] = __floats2half2_rn(s.v[6], s.v[7]);
    out_h[row * 8 + lane] = o.u;

    int a0 = row * 16 + lane * 2;
    float4 p = g_acc[a0];
    float4 q = g_acc[a0 + 1];
    p.x += s.v[0]; p.y += s.v[1]; p.z += s.v[2]; p.w += s.v[3];
    q.x += s.v[4]; q.y += s.v[5]; q.z += s.v[6]; q.w += s.v[7];
    g_acc[a0]     = p;
    g_acc[a0 + 1] = q;
}

// Layer 3: out = 0.25 * (acc + A*in)
__global__ void spmm_final_kernel(const uint4* __restrict__ in,
                                  float4*      __restrict__ out) {
    int gtid = blockIdx.x * blockDim.x + threadIdx.x;
    int row  = gtid >> 3;
    int lane = gtid & 7;
    if (row >= NNODES) return;

    Acc8 s = spmm_row(in, row, lane);

    int a0 = row * 16 + lane * 2;
    float4 p = g_acc[a0];
    float4 q = g_acc[a0 + 1];
    float4 r0, r1;
    r0.x = 0.25f * (p.x + s.v[0]);
    r0.y = 0.25f * (p.y + s.v[1]);
    r0.z = 0.25f * (p.z + s.v[2]);
    r0.w = 0.25f * (p.w + s.v[3]);
    r1.x = 0.25f * (q.x + s.v[4]);
    r1.y = 0.25f * (q.y + s.v[5]);
    r1.z = 0.25f * (q.z + s.v[6]);
    r1.w = 0.25f * (q.w + s.v[7]);
    out[a0]     = r0;
    out[a0 + 1] = r1;
}

// ---------------- launch ----------------

extern "C" void kernel_launch(void* const* d_in, const int* in_sizes, int n_in,
                              void* d_out, int out_size) {
    const float4* user = (const float4*)d_in[0];
    const float4* item = (const float4*)d_in[1];
    const int*    esrc = (const int*)d_in[2];
    const int*    edst = (const int*)d_in[3];
    const float*  eval = (const float*)d_in[4];
    float4* out = (float4*)d_out;

    uint4 *h0, *h1;
    cudaGetSymbolAddress((void**)&h0, g_h0);
    cudaGetSymbolAddress((void**)&h1, g_h1);

    const int TB = 256;
    int node_blocks = (NNODES + TB - 1) / TB;
    int edge_blocks = (NNZ_E + TB - 1) / TB;
    int hvec_blocks = (HVEC + TB - 1) / TB;          // also spmm grid (8 lanes/row)

    // CSR build
    zero_counts<<<node_blocks, TB>>>();
    hist_kernel<<<edge_blocks, TB>>>(esrc);
    scan_local<<<SCAN_NBLK, SCAN_B>>>();
    scan_sums<<<1, 1024>>>();
    scan_add<<<SCAN_NBLK, SCAN_B>>>();
    scatter_kernel<<<edge_blocks, TB>>>(esrc, edst, eval);

    // init: h0 = fp16(concat), acc = concat
    init_kernel<<<hvec_blocks, TB>>>(user, item);

    // 3 layers; layer 3 fuses the residual average into d_out
    spmm_kernel<<<hvec_blocks, TB>>>(h0, h1);
    spmm_kernel<<<hvec_blocks, TB>>>(h1, h0);
    spmm_final_kernel<<<hvec_blocks, TB>>>(h0, out);
}

// round 6
// speedup vs baseline: 2.9806x; 1.1055x over previous
#include <cuda_runtime.h>
#include <cuda_fp16.h>
#include <cuda_bf16.h>

// LightGCN: CSR SpMM x3, fp16 feature buffers, fp32 row accumulation.
// Round 6 (resubmit of R5 after infra failure): no fp32 residual-acc buffer
// (working set 114MB -> 76MB, keeps layers fully L2-resident and saves 77MB
// RMW traffic per layer); final kernel sums h0+h1+h2+s3 directly. CSR build:
// memsetAsync zeroing, single-pass decoupled-lookback scan, scatter fused
// with init.

constexpr int NUSERS = 100000;
constexpr int NITEMS = 50000;
constexpr int NNODES = 150000;
constexpr int NNZ_E  = 4800000;
constexpr int HVEC   = NNODES * 8;    // uint4 (8 halves) per fp16 buffer

constexpr int TB          = 256;
constexpr int SCAN_NBLK   = (NNODES + TB - 1) / TB;      // 586
constexpr int EDGE_BLOCKS = (NNZ_E + TB - 1) / TB;       // 18750
constexpr int HVEC_BLOCKS = (HVEC + TB - 1) / TB;        // 4688

// ---- scratch ----
struct ZeroRegion {                    // zeroed with ONE cudaMemsetAsync
    int cnt[NNODES];
    unsigned long long state[SCAN_NBLK];
    unsigned int ticket;
};
__device__ ZeroRegion g_zs;
__device__ uint4 g_h0[HVEC];
__device__ uint4 g_h1[HVEC];
__device__ uint4 g_h2[HVEC];
__device__ int   g_rowptr[NNODES + 1];
__device__ int   g_rowcur[NNODES];
__device__ int2  g_meta[NNZ_E];        // {dst, val bits} sorted by src

// ---------------- CSR build ----------------

__global__ void hist_kernel(const int4* __restrict__ src4) {
    int t = blockIdx.x * blockDim.x + threadIdx.x;
    if (t < NNZ_E / 4) {
        int4 s = __ldg(&src4[t]);
        atomicAdd(&g_zs.cnt[s.x], 1);
        atomicAdd(&g_zs.cnt[s.y], 1);
        atomicAdd(&g_zs.cnt[s.z], 1);
        atomicAdd(&g_zs.cnt[s.w], 1);
    }
}

// Single-pass exclusive scan with decoupled lookback.
__global__ void scan_onepass() {
    __shared__ int s[TB];
    __shared__ int sbid;
    __shared__ int sprefix;
    int tid = threadIdx.x;
    if (tid == 0) {
        sbid = (int)atomicAdd(&g_zs.ticket, 1u);
        sprefix = 0;
    }
    __syncthreads();
    int bid = sbid;
    int i = bid * TB + tid;
    int v = (i < NNODES) ? g_zs.cnt[i] : 0;
    s[tid] = v;
    __syncthreads();
    #pragma unroll
    for (int off = 1; off < TB; off <<= 1) {
        int x = (tid >= off) ? s[tid - off] : 0;
        __syncthreads();
        s[tid] += x;
        __syncthreads();
    }
    int incl  = s[tid];
    int total = s[TB - 1];

    if (tid == 0) {
        unsigned long long pkt =
            ((unsigned long long)((bid == 0) ? 2u : 1u) << 32) | (unsigned int)total;
        atomicExch(&g_zs.state[bid], pkt);
    }

    if (bid > 0 && tid < 32) {
        int look = bid - 1;
        int pfx = 0;
        for (;;) {
            int j = look - tid;
            int flag, val;
            if (j >= 0) {
                unsigned long long pkt;
                do {
                    pkt = atomicAdd(&g_zs.state[j], 0ULL);
                    flag = (int)(pkt >> 32);
                } while (flag == 0);
                val = (int)(unsigned int)pkt;
            } else { flag = 2; val = 0; }
            unsigned int ball = __ballot_sync(0xffffffffu, flag == 2);
            int first = __ffs(ball) - 1;         // -1 if none
            int contrib = (first < 0) ? val : ((tid <= first) ? val : 0);
            #pragma unroll
            for (int o = 16; o; o >>= 1)
                contrib += __shfl_down_sync(0xffffffffu, contrib, o);
            if (tid == 0) pfx += contrib;
            if (ball) break;
            look -= 32;
        }
        if (tid == 0) {
            sprefix = pfx;
            atomicExch(&g_zs.state[bid],
                       ((unsigned long long)2u << 32) | (unsigned int)(total + pfx));
        }
    }
    __syncthreads();
    int excl = sprefix + incl - v;
    if (i < NNODES) {
        g_rowptr[i] = excl;
        g_rowcur[i] = excl;
    }
    if (i == NNODES - 1) g_rowptr[NNODES] = NNZ_E;
}

// scatter (first EDGE_BLOCKS blocks) fused with init h0 (rest).
__global__ void scatter_init_kernel(const int*    __restrict__ src,
                                    const int*    __restrict__ dst,
                                    const float*  __restrict__ val,
                                    const float4* __restrict__ user,
                                    const float4* __restrict__ item) {
    if (blockIdx.x < EDGE_BLOCKS) {
        int e = blockIdx.x * TB + threadIdx.x;
        if (e < NNZ_E) {
            int sN = __ldg(&src[e]);
            int pos = atomicAdd(&g_rowcur[sN], 1);
            g_meta[pos] = make_int2(__ldg(&dst[e]), __float_as_int(__ldg(&val[e])));
        }
    } else {
        int i = (blockIdx.x - EDGE_BLOCKS) * TB + threadIdx.x;
        if (i < HVEC) {
            int j = i * 2;
            float4 a = (j     < NUSERS * 16) ? __ldg(&user[j])     : __ldg(&item[j - NUSERS * 16]);
            float4 b = (j + 1 < NUSERS * 16) ? __ldg(&user[j + 1]) : __ldg(&item[j + 1 - NUSERS * 16]);
            union { uint4 u; __half2 h[4]; } o;
            o.h[0] = __floats2half2_rn(a.x, a.y);
            o.h[1] = __floats2half2_rn(a.z, a.w);
            o.h[2] = __floats2half2_rn(b.x, b.y);
            o.h[3] = __floats2half2_rn(b.z, b.w);
            g_h0[i] = o.u;
        }
    }
}

// ---------------- SpMM core: 8 lanes/row, 8 floats/lane ----------------

struct Acc8 { float v[8]; };

__device__ __forceinline__ void fma8(Acc8& a, float w, uint4 u) {
    union { uint4 u; __half2 h[4]; } x;
    x.u = u;
    #pragma unroll
    for (int k = 0; k < 4; k++) {
        float2 f = __half22float2(x.h[k]);
        a.v[2*k]   += w * f.x;
        a.v[2*k+1] += w * f.y;
    }
}

__device__ __forceinline__ Acc8 spmm_row(const uint4* __restrict__ in,
                                         int row, int lane) {
    int beg = __ldg(&g_rowptr[row]);
    int end = __ldg(&g_rowptr[row + 1]);
    Acc8 acc;
    #pragma unroll
    for (int k = 0; k < 8; k++) acc.v[k] = 0.f;
    int i = beg;
    for (; i + 4 <= end; i += 4) {
        int2 m0 = __ldg(&g_meta[i]);
        int2 m1 = __ldg(&g_meta[i + 1]);
        int2 m2 = __ldg(&g_meta[i + 2]);
        int2 m3 = __ldg(&g_meta[i + 3]);
        uint4 x0 = __ldg(&in[m0.x * 8 + lane]);
        uint4 x1 = __ldg(&in[m1.x * 8 + lane]);
        uint4 x2 = __ldg(&in[m2.x * 8 + lane]);
        uint4 x3 = __ldg(&in[m3.x * 8 + lane]);
        fma8(acc, __int_as_float(m0.y), x0);
        fma8(acc, __int_as_float(m1.y), x1);
        fma8(acc, __int_as_float(m2.y), x2);
        fma8(acc, __int_as_float(m3.y), x3);
    }
    for (; i < end; i++) {
        int2 m = __ldg(&g_meta[i]);
        uint4 x = __ldg(&in[m.x * 8 + lane]);
        fma8(acc, __int_as_float(m.y), x);
    }
    return acc;
}

// Layers 1,2: out_h = fp16(A * in)
__global__ void spmm_kernel(const uint4* __restrict__ in,
                            uint4*       __restrict__ out_h) {
    int gtid = blockIdx.x * blockDim.x + threadIdx.x;
    int row  = gtid >> 3;
    int lane = gtid & 7;
    if (row >= NNODES) return;

    Acc8 s = spmm_row(in, row, lane);

    union { uint4 u; __half2 h[4]; } o;
    o.h[0] = __floats2half2_rn(s.v[0], s.v[1]);
    o.h[1] = __floats2half2_rn(s.v[2], s.v[3]);
    o.h[2] = __floats2half2_rn(s.v[4], s.v[5]);
    o.h[3] = __floats2half2_rn(s.v[6], s.v[7]);
    out_h[row * 8 + lane] = o.u;
}

// Layer 3 + epilogue: out = 0.25 * (h0 + h1 + h2 + A*h2)
__global__ void spmm_final_kernel(float4* __restrict__ out) {
    int gtid = blockIdx.x * blockDim.x + threadIdx.x;
    int row  = gtid >> 3;
    int lane = gtid & 7;
    if (row >= NNODES) return;

    Acc8 s = spmm_row(g_h2, row, lane);

    int hidx = row * 8 + lane;
    union { uint4 u; __half2 h[4]; } a, b, c;
    a.u = g_h0[hidx];
    b.u = g_h1[hidx];
    c.u = g_h2[hidx];

    float r[8];
    #pragma unroll
    for (int k = 0; k < 4; k++) {
        float2 fa = __half22float2(a.h[k]);
        float2 fb = __half22float2(b.h[k]);
        float2 fc = __half22float2(c.h[k]);
        r[2*k]   = 0.25f * (fa.x + fb.x + fc.x + s.v[2*k]);
        r[2*k+1] = 0.25f * (fa.y + fb.y + fc.y + s.v[2*k+1]);
    }
    int o0 = row * 16 + lane * 2;
    out[o0]     = make_float4(r[0], r[1], r[2], r[3]);
    out[o0 + 1] = make_float4(r[4], r[5], r[6], r[7]);
}

// ---------------- launch ----------------

extern "C" void kernel_launch(void* const* d_in, const int* in_sizes, int n_in,
                              void* d_out, int out_size) {
    const float4* user = (const float4*)d_in[0];
    const float4* item = (const float4*)d_in[1];
    const int*    esrc = (const int*)d_in[2];
    const int*    edst = (const int*)d_in[3];
    const float*  eval = (const float*)d_in[4];
    float4* out = (float4*)d_out;

    uint4 *h0, *h1, *h2;
    void* zs;
    cudaGetSymbolAddress((void**)&h0, g_h0);
    cudaGetSymbolAddress((void**)&h1, g_h1);
    cudaGetSymbolAddress((void**)&h2, g_h2);
    cudaGetSymbolAddress(&zs, g_zs);

    // zero counts + scan state + ticket in one memset node
    cudaMemsetAsync(zs, 0, sizeof(ZeroRegion));

    hist_kernel<<<(NNZ_E / 4 + TB - 1) / TB, TB>>>((const int4*)esrc);
    scan_onepass<<<SCAN_NBLK, TB>>>();
    scatter_init_kernel<<<EDGE_BLOCKS + HVEC_BLOCKS, TB>>>(esrc, edst, eval, user, item);

    spmm_kernel<<<HVEC_BLOCKS, TB>>>(h0, h1);
    spmm_kernel<<<HVEC_BLOCKS, TB>>>(h1, h2);
    spmm_final_kernel<<<HVEC_BLOCKS, TB>>>(out);
}